// round 11
// baseline (speedup 1.0000x reference)
#include <cuda_runtime.h>
#include <math.h>

#define BC     4
#define NODES  4096
#define FEAT   64
#define OUTD   32
#define NEDGES (32 * NODES)
#define NW     (NODES / 32)   // 128 bitmap words per row
#define CAPW   128            // per-warp neighbor capacity (deg ~ Poisson(32))

// Scratch (no allocations in kernel_launch). g_bits is zero at module load;
// k_gat re-zeroes every word it consumes, so the bitmap is always clear when
// k_z_set's atomicOr scatter runs on the next call/replay.
// z stored batch-PAIR interleaved: g_z2[pair][node][feat] = (z_{2p}, z_{2p+1})
__device__ float2   g_z2[2 * NODES * OUTD];   // 2 MB
__device__ unsigned g_bits[NODES * NW];       // 2 MB

// ---------------------------------------------------------------------------
// Fused: z = h @ W (2 rows/warp; h warp-uniform float4, W staged in smem) +
// edge scatter. Writes into the pair-interleaved layout.
__global__ __launch_bounds__(256) void k_z_set(const float* __restrict__ h,
                                               const float* __restrict__ W,
                                               const int* __restrict__ erow,
                                               const int* __restrict__ ecol) {
    __shared__ __align__(16) float Ws[FEAT * OUTD];       // 8 KB
    const int tid = threadIdx.x;
    ((float4*)Ws)[tid]       = ((const float4*)W)[tid];
    ((float4*)Ws)[tid + 256] = ((const float4*)W)[tid + 256];

    const int gid = blockIdx.x * 256 + tid;
    if (gid < NEDGES) {
        const int r = erow[gid], c = ecol[gid];
        atomicOr(&g_bits[r * NW + (c >> 5)], 1u << (c & 31));
    }
    __syncthreads();

    const int lane = tid & 31, wid = tid >> 5;
    const int r0 = (blockIdx.x * 8 + wid) * 2;     // global row in [0, BC*NODES)
    const int b  = r0 / NODES;                     // r0,r0+1 share batch
    const int n  = r0 - b * NODES;
    const int pair = b >> 1, comp = b & 1;
    const float4* h4 = (const float4*)(h + (long)r0 * FEAT);
    float a0 = 0.f, a1 = 0.f;
#pragma unroll
    for (int q = 0; q < 16; q++) {
        const float4 h0 = h4[q];
        const float4 h1 = h4[16 + q];
        const float w0 = Ws[(4 * q + 0) * OUTD + lane];
        const float w1 = Ws[(4 * q + 1) * OUTD + lane];
        const float w2 = Ws[(4 * q + 2) * OUTD + lane];
        const float w3 = Ws[(4 * q + 3) * OUTD + lane];
        a0 = fmaf(h0.x, w0, a0); a0 = fmaf(h0.y, w1, a0);
        a0 = fmaf(h0.z, w2, a0); a0 = fmaf(h0.w, w3, a0);
        a1 = fmaf(h1.x, w0, a1); a1 = fmaf(h1.y, w1, a1);
        a1 = fmaf(h1.z, w2, a1); a1 = fmaf(h1.w, w3, a1);
    }
    float* gz = (float*)g_z2;
    gz[(((long)pair * NODES + n)     * OUTD + lane) * 2 + comp] = a0;
    gz[(((long)pair * NODES + n + 1) * OUTD + lane) * 2 + comp] = a1;
}

// ---------------------------------------------------------------------------
// Order-preserving float<->uint transform for __reduce_max_sync.
__device__ __forceinline__ unsigned f2ord(float f) {
    unsigned u = __float_as_uint(f);
    return (u & 0x80000000u) ? ~u : (u | 0x80000000u);
}
__device__ __forceinline__ float ord2f(unsigned u) {
    return __uint_as_float((u & 0x80000000u) ? (u & 0x7fffffffu) : ~u);
}

// One 64-thread block per destination row; warp w owns batch PAIR (2w, 2w+1).
// Tile row: 32 float2 (= 16 f4), padded to 17 f4 for conflict-freedom.
#define TROWS 16
#define RF4   17                               // f4 stride per tile row
__global__ __launch_bounds__(64, 18) void k_gat(float* __restrict__ out) {
    __shared__ unsigned short nbr[2][CAPW];
    __shared__ __align__(16) float  tile[2][TROWS * RF4 * 4];
    __shared__ __align__(16) float2 s_zi[2][OUTD];
    __shared__ __align__(16) float2 s_e[2][TROWS];

    const int row  = blockIdx.x;
    const int tid  = threadIdx.x;
    const int lane = tid & 31, wid = tid >> 5;

    const float2* zb2 = g_z2 + (long)wid * NODES * OUTD;
    const float4* zb4 = (const float4*)zb2;         // 16 f4 per node row

    // overlapping prefetches: z_i (both batches) + this lane's 4 bitmap words
    const float2 zi2 = zb2[row * OUTD + lane];
    const uint4 wv = ((const uint4*)(g_bits + row * NW))[lane];
    s_zi[wid][lane] = zi2;

    __syncthreads();                          // both warps have read the bitmap
    if (tid < 32)                             // leave bitmap clean for next run
        ((uint4*)(g_bits + row * NW))[tid] = make_uint4(0u, 0u, 0u, 0u);

    // --- Phase A (per-warp): count, scan, extract ---
    const int cnt = __popc(wv.x) + __popc(wv.y) + __popc(wv.z) + __popc(wv.w);
    int v = cnt;
#pragma unroll
    for (int o = 1; o < 32; o <<= 1) {
        int t = __shfl_up_sync(0xffffffffu, v, o);
        if (lane >= o) v += t;
    }
    int M = __shfl_sync(0xffffffffu, v, 31);
    int off = v - cnt;
    const int cb = lane * 128;
    unsigned ws[4] = {wv.x, wv.y, wv.z, wv.w};
#pragma unroll
    for (int q = 0; q < 4; q++) {
        unsigned ww = ws[q];
        while (ww) {
            int b = __ffs(ww) - 1;
            if (off < CAPW) nbr[wid][off] = (unsigned short)(cb + q * 32 + b);
            off++;
            ww &= ww - 1;
        }
    }
    if (M > CAPW) M = CAPW;                   // never hit in practice
    __syncwarp();                             // nbr[wid] is warp-private

    // --- Phase B: warp `wid` = batches (2*wid, 2*wid+1) ---
    float4*       tw4  = (float4*)tile[wid];
    const float2* twl2 = ((const float2*)tile[wid]) + lane;   // feature = lane
    const float4* z4   = (const float4*)s_zi[wid];            // 16 f4
    const float4* se4  = (const float4*)s_e[wid];             // 8 f4
    const int kn   = lane >> 1;               // neighbor slot 0..15
    const int half = lane & 1;                // feature half of the dot

    float m0 = -INFINITY, m1 = -INFINITY, ss0 = 0.f, ss1 = 0.f;
    float2 accA = make_float2(0.f, 0.f), accB = make_float2(0.f, 0.f);

    for (int t = 0; t < M; t += TROWS) {
        const int  rem = (M - t < TROWS) ? (M - t) : TROWS;   // warp-uniform
        const bool inr = (kn < rem);
        const int  j   = nbr[wid][t + (inr ? kn : 0)];        // clamped

        // stage 16 node rows x 16 f4 (256B each, BOTH batches) = 8 f4/lane
#pragma unroll
        for (int i = 0; i < 8; i++) {
            const int e  = i * 32 + lane;
            const int k  = e >> 4, d4 = e & 15;
            const int jk = __shfl_sync(0xffffffffu, j, 2 * k);
            tw4[k * RF4 + d4] = zb4[jk * 16 + d4];
        }
        __syncwarp();

        // half-dot for BOTH batches: features [16*half, 16*half+16)
        float p0a = 0.f, p0b = 0.f, p1a = 0.f, p1b = 0.f;
#pragma unroll
        for (int i = 0; i < 8; i++) {
            const float4 vv = tw4[kn * RF4 + half * 8 + i];   // (f:b0,b1, f+1:b0,b1)
            const float4 zz = z4[half * 8 + i];
            p0a = fmaf(vv.x, zz.x, p0a);
            p1a = fmaf(vv.y, zz.y, p1a);
            p0b = fmaf(vv.z, zz.z, p0b);
            p1b = fmaf(vv.w, zz.w, p1b);
        }
        float p0 = p0a + p0b, p1 = p1a + p1b;
        p0 += __shfl_xor_sync(0xffffffffu, p0, 1);
        p1 += __shfl_xor_sync(0xffffffffu, p1, 1);
        const float s0 = (p0 >= 0.f) ? p0 : 0.1f * p0;        // LeakyReLU(0.1)
        const float s1 = (p1 >= 0.f) ? p1 : 0.1f * p1;
        const bool  v0 = inr && (s0 != 0.f);                  // att==0 -> masked
        const bool  v1 = inr && (s1 != 0.f);
        const float sv0 = v0 ? s0 : -INFINITY;
        const float sv1 = v1 ? s1 : -INFINITY;

        const float tm0 = ord2f(__reduce_max_sync(0xffffffffu, f2ord(sv0)));
        const float tm1 = ord2f(__reduce_max_sync(0xffffffffu, f2ord(sv1)));
        const float nm0 = fmaxf(m0, tm0), nm1 = fmaxf(m1, tm1);
        const float ns0 = (nm0 > -INFINITY) ? nm0 : 0.f;      // NaN guard
        const float ns1 = (nm1 > -INFINITY) ? nm1 : 0.f;
        const float c0 = __expf(m0 - ns0);                    // 0 when m=-inf
        const float c1 = __expf(m1 - ns1);
        const float e0 = v0 ? __expf(sv0 - ns0) : 0.f;
        const float e1 = v1 ? __expf(sv1 - ns1) : 0.f;
        if (half == 0) s_e[wid][kn] = make_float2(e0, e1);
        m0 = nm0;  m1 = nm1;
        accA.x *= c0;  accB.x *= c0;  ss0 *= c0;
        accA.y *= c1;  accB.y *= c1;  ss1 *= c1;
        __syncwarp();

        // aggregation: 8 x (e-f4 bcast + 2 tile LDS.64 + 4 FMA), both batches
        float es0 = 0.f, es1 = 0.f;
#pragma unroll
        for (int k4 = 0; k4 < 8; k4++) {
            const float4 ev = se4[k4];                  // slots 2k4, 2k4+1
            const float2 t0v = twl2[(2 * k4)     * (RF4 * 2)];
            const float2 t1v = twl2[(2 * k4 + 1) * (RF4 * 2)];
            accA.x = fmaf(ev.x, t0v.x, accA.x);
            accA.y = fmaf(ev.y, t0v.y, accA.y);
            accB.x = fmaf(ev.z, t1v.x, accB.x);
            accB.y = fmaf(ev.w, t1v.y, accB.y);
            es0 += ev.x + ev.z;  es1 += ev.y + ev.w;
        }
        ss0 += es0;  ss1 += es1;
        __syncwarp();
    }

    float o0, o1;
    if (m0 > -INFINITY) {
        o0 = (accA.x + accB.x) / ss0;
    } else {                     // fully-masked row: uniform over ALL columns
        float s2 = 0.f;
        for (int n = 0; n < NODES; n++) s2 += zb2[n * OUTD + lane].x;
        o0 = s2 * (1.f / (float)NODES);
    }
    if (m1 > -INFINITY) {
        o1 = (accA.y + accB.y) / ss1;
    } else {
        float s2 = 0.f;
        for (int n = 0; n < NODES; n++) s2 += zb2[n * OUTD + lane].y;
        o1 = s2 * (1.f / (float)NODES);
    }
    out[((2 * wid)     * NODES + row) * OUTD + lane] = o0;
    out[((2 * wid + 1) * NODES + row) * OUTD + lane] = o1;
}

// ---------------------------------------------------------------------------
extern "C" void kernel_launch(void* const* d_in, const int* in_sizes, int n_in,
                              void* d_out, int out_size) {
    const float* h       = (const float*)d_in[0];
    const float* W       = (const float*)d_in[1];
    const int*   adj_row = (const int*)d_in[2];
    const int*   adj_col = (const int*)d_in[3];
    float*       out     = (float*)d_out;

    k_z_set<<<(BC * NODES) / 16, 256>>>(h, W, adj_row, adj_col);
    k_gat  <<<NODES, 64>>>(out);
}